// round 10
// baseline (speedup 1.0000x reference)
#include <cuda_runtime.h>
#include <cuda_fp16.h>
#include <cstdint>

#define E_CAP 100000
#define M_CAP 1000000
#define NTILE_CAP 128

// -------- device scratch --------
__device__ __half   g_Vh[(size_t)E_CAP * 128];   // V projection [E,128] fp16
__device__ float    g_expk[E_CAP * 8];           // exp(kA) per edge/head
__device__ int      g_cnt[E_CAP];                // per-dst pair counts
__device__ int      g_rowptr[E_CAP + 1];         // CSR row pointers
__device__ int      g_head[E_CAP];               // scatter cursors
__device__ int      g_ssort[M_CAP];              // src ids sorted by dst
__device__ int      g_idx64;
// decoupled-lookback state
__device__ int          g_ticket;
__device__ volatile int g_tstate[NTILE_CAP];     // 0=invalid 1=agg 2=prefix
__device__ int          g_tagg[NTILE_CAP];
__device__ int          g_tpre[NTILE_CAP];

__device__ __forceinline__ int ld_idx(const void* idx, long long pos, int is64) {
    return is64 ? (int)((const long long*)idx)[pos] : ((const int*)idx)[pos];
}
__device__ __forceinline__ unsigned f2tf(float f) {
    unsigned u; asm("cvt.rna.tf32.f32 %0, %1;" : "=r"(u) : "f"(f)); return u;
}
__device__ __forceinline__ void cp16(void* smem_dst, const void* gptr) {
    unsigned saddr = (unsigned)__cvta_generic_to_shared(smem_dst);
    asm volatile("cp.async.cg.shared.global [%0], [%1], 16;" :: "r"(saddr), "l"(gptr));
}

// -------- merged: zero counters + detect index dtype + reset lookback state ----
__global__ void init_detect_kernel(const void* __restrict__ idx, int E) {
    int i = blockIdx.x * blockDim.x + threadIdx.x;
    if (i < E) g_cnt[i] = 0;
    if (i < NTILE_CAP) g_tstate[i] = 0;
    if (i == 0) {
        g_ticket = 0;
        const long long* p = (const long long*)idx;
        int ok = 1;
        for (int q = 0; q < 64; q++) {
            long long v = p[q];
            if (v < 0 || v >= (long long)E) { ok = 0; break; }
        }
        g_idx64 = ok;
    }
}

// -------- K1: Vh(fp16) = edge_attr @ Wv + bv  AND  expk = exp(edge_attr·wkA + bkA) ----
// tf32 mma.sync m16n8k8, cp.async double-buffered; Wk·Aw contraction folded into prologue.
#define AS_OFF 0
#define BS_OFF (2 * 128 * 36)
#define WK_OFF (BS_OFF + 2 * 32 * 132)
#define BK_OFF (WK_OFF + 8 * 132)
#define SMEM_FLOATS (BK_OFF + 8)

__global__ void __launch_bounds__(256) gemm_vh_tf32_kernel(
    const float* __restrict__ A, const float* __restrict__ B,
    const float* __restrict__ bias,
    const float* __restrict__ Wk, const float* __restrict__ bk,
    const float* __restrict__ Aw, int E)
{
    extern __shared__ float sm[];
    float* As  = sm + AS_OFF;   // buf*4608 + row*36 + k
    float* Bs  = sm + BS_OFF;   // buf*4224 + k*132 + n
    float* Wks = sm + WK_OFF;   // h*132 + k
    float* bks = sm + BK_OFF;

    const int t = threadIdx.x;
    const int warp = t >> 5, lane = t & 31;
    const int gid = lane >> 2, tid4 = lane & 3;
    const int wm = warp & 3, wn = warp >> 2;
    const int row0 = blockIdx.x * 128;

    const int a_row = t >> 3, a_c4 = t & 7;
    const int b_k   = t >> 5, b_n4 = t & 31;

    // prologue: prefetch chunk 0 into buf 0 (issue ASAP)
    {
        #pragma unroll
        for (int p = 0; p < 4; p++) {
            int row = a_row + p * 32;
            int grow = row0 + row; if (grow >= E) grow = E - 1;
            cp16(&As[row * 36 + a_c4 * 4], A + (size_t)grow * 128 + a_c4 * 4);
        }
        #pragma unroll
        for (int p = 0; p < 4; p++) {
            int kk = b_k + p * 8;
            cp16(&Bs[kk * 132 + b_n4 * 4], B + (size_t)kk * 128 + b_n4 * 4);
        }
        asm volatile("cp.async.commit_group;");
    }

    // fold prep: Wks[h][k] = sum_d Wk[k*128+h*16+d]*Aw[d*8+h] (4 entries/thread)
    #pragma unroll
    for (int q = 0; q < 4; q++) {
        int i = t + q * 256;             // i = h*128 + k
        int h = i >> 7, k = i & 127;
        float s = 0.f;
        #pragma unroll
        for (int d = 0; d < 16; d++) s += Wk[k * 128 + h * 16 + d] * Aw[d * 8 + h];
        Wks[h * 132 + k] = s;
    }
    if (t < 8) {
        float s = 0.f;
        #pragma unroll
        for (int d = 0; d < 16; d++) s += bk[t * 16 + d] * Aw[d * 8 + t];
        bks[t] = s;
    }

    float c[2][8][4];
    #pragma unroll
    for (int i = 0; i < 2; i++)
        #pragma unroll
        for (int j = 0; j < 8; j++)
            #pragma unroll
            for (int r = 0; r < 4; r++) c[i][j][r] = 0.f;
    float kc[2][4] = {};

    #pragma unroll
    for (int i = 0; i < 4; i++) {
        const int k0 = i * 32;
        if (i < 3) {
            const int kn = k0 + 32;
            float* Ad = As + ((i + 1) & 1) * 4608;
            float* Bd = Bs + ((i + 1) & 1) * 4224;
            #pragma unroll
            for (int p = 0; p < 4; p++) {
                int row = a_row + p * 32;
                int grow = row0 + row; if (grow >= E) grow = E - 1;
                cp16(&Ad[row * 36 + a_c4 * 4], A + (size_t)grow * 128 + kn + a_c4 * 4);
            }
            #pragma unroll
            for (int p = 0; p < 4; p++) {
                int kk = b_k + p * 8;
                cp16(&Bd[kk * 132 + b_n4 * 4], B + (size_t)(kn + kk) * 128 + b_n4 * 4);
            }
            asm volatile("cp.async.commit_group;");
            asm volatile("cp.async.wait_group 1;");
        } else {
            asm volatile("cp.async.wait_group 0;");
        }
        __syncthreads();

        const float* Ab = As + (i & 1) * 4608;
        const float* Bb = Bs + (i & 1) * 4224;

        #pragma unroll
        for (int ks = 0; ks < 4; ks++) {
            const int kb = ks * 8;
            unsigned af[2][4];
            #pragma unroll
            for (int ma = 0; ma < 2; ma++) {
                int ar = wm * 32 + ma * 16;
                af[ma][0] = f2tf(Ab[(ar + gid    ) * 36 + kb + tid4]);
                af[ma][1] = f2tf(Ab[(ar + gid + 8) * 36 + kb + tid4]);
                af[ma][2] = f2tf(Ab[(ar + gid    ) * 36 + kb + tid4 + 4]);
                af[ma][3] = f2tf(Ab[(ar + gid + 8) * 36 + kb + tid4 + 4]);
            }
            #pragma unroll
            for (int na = 0; na < 8; na++) {
                int bc = wn * 64 + na * 8 + gid;
                unsigned b0 = f2tf(Bb[(kb + tid4    ) * 132 + bc]);
                unsigned b1 = f2tf(Bb[(kb + tid4 + 4) * 132 + bc]);
                #pragma unroll
                for (int ma = 0; ma < 2; ma++) {
                    asm volatile(
                        "mma.sync.aligned.m16n8k8.row.col.f32.tf32.tf32.f32 "
                        "{%0,%1,%2,%3}, {%4,%5,%6,%7}, {%8,%9}, {%0,%1,%2,%3};"
                        : "+f"(c[ma][na][0]), "+f"(c[ma][na][1]),
                          "+f"(c[ma][na][2]), "+f"(c[ma][na][3])
                        : "r"(af[ma][0]), "r"(af[ma][1]), "r"(af[ma][2]), "r"(af[ma][3]),
                          "r"(b0), "r"(b1));
                }
            }
            if (wn == 0) {   // fused kA: B2[k][h] = Wks[h][k]
                unsigned b0 = f2tf(Wks[gid * 132 + k0 + kb + tid4]);
                unsigned b1 = f2tf(Wks[gid * 132 + k0 + kb + tid4 + 4]);
                #pragma unroll
                for (int ma = 0; ma < 2; ma++) {
                    asm volatile(
                        "mma.sync.aligned.m16n8k8.row.col.f32.tf32.tf32.f32 "
                        "{%0,%1,%2,%3}, {%4,%5,%6,%7}, {%8,%9}, {%0,%1,%2,%3};"
                        : "+f"(kc[ma][0]), "+f"(kc[ma][1]),
                          "+f"(kc[ma][2]), "+f"(kc[ma][3])
                        : "r"(af[ma][0]), "r"(af[ma][1]), "r"(af[ma][2]), "r"(af[ma][3]),
                          "r"(b0), "r"(b1));
                }
            }
        }
        __syncthreads();
    }

    // epilogue: Vh = half(c + bias)
    #pragma unroll
    for (int ma = 0; ma < 2; ma++) {
        int r_base = row0 + wm * 32 + ma * 16 + gid;
        #pragma unroll
        for (int na = 0; na < 8; na++) {
            int col = wn * 64 + na * 8 + 2 * tid4;
            float b0 = bias[col], b1 = bias[col + 1];
            if (r_base < E) {
                __half2 p = __floats2half2_rn(c[ma][na][0] + b0, c[ma][na][1] + b1);
                *(__half2*)(g_Vh + (size_t)r_base * 128 + col) = p;
            }
            if (r_base + 8 < E) {
                __half2 p = __floats2half2_rn(c[ma][na][2] + b0, c[ma][na][3] + b1);
                *(__half2*)(g_Vh + (size_t)(r_base + 8) * 128 + col) = p;
            }
        }
    }
    if (wn == 0) {
        int h0 = 2 * tid4;
        float bk0 = bks[h0], bk1 = bks[h0 + 1];
        #pragma unroll
        for (int ma = 0; ma < 2; ma++) {
            int r = row0 + wm * 32 + ma * 16 + gid;
            if (r < E) {
                g_expk[r * 8 + h0    ] = __expf(kc[ma][0] + bk0);
                g_expk[r * 8 + h0 + 1] = __expf(kc[ma][1] + bk1);
            }
            if (r + 8 < E) {
                g_expk[(r + 8) * 8 + h0    ] = __expf(kc[ma][2] + bk0);
                g_expk[(r + 8) * 8 + h0 + 1] = __expf(kc[ma][3] + bk1);
            }
        }
    }
}

// -------- hist: 4 pairs per thread, vector loads ----
__global__ void hist_kernel(const void* __restrict__ idx, int Mp) {
    int m0 = (blockIdx.x * blockDim.x + threadIdx.x) * 4;
    if (m0 >= Mp) return;
    int is64 = g_idx64;
    if (m0 + 3 < Mp) {
        if (is64) {
            const longlong2* p = (const longlong2*)((const long long*)idx + Mp + m0);
            longlong2 a = p[0], b = p[1];
            atomicAdd(&g_cnt[(int)a.x], 1); atomicAdd(&g_cnt[(int)a.y], 1);
            atomicAdd(&g_cnt[(int)b.x], 1); atomicAdd(&g_cnt[(int)b.y], 1);
        } else {
            int4 a = *(const int4*)((const int*)idx + Mp + m0);
            atomicAdd(&g_cnt[a.x], 1); atomicAdd(&g_cnt[a.y], 1);
            atomicAdd(&g_cnt[a.z], 1); atomicAdd(&g_cnt[a.w], 1);
        }
    } else {
        for (int r = 0; r < 4 && m0 + r < Mp; r++)
            atomicAdd(&g_cnt[ld_idx(idx, (long long)Mp + m0 + r, is64)], 1);
    }
}

// -------- single-pass exclusive scan with decoupled lookback ----
__global__ void __launch_bounds__(1024) scan_lookback_kernel(int E, int Mp) {
    __shared__ int s_tile, s_exc;
    __shared__ int ws[32];
    if (threadIdx.x == 0) s_tile = atomicAdd(&g_ticket, 1);
    __syncthreads();
    const int tile = s_tile;
    const int i = tile * 1024 + threadIdx.x;
    const int c = (i < E) ? g_cnt[i] : 0;

    // block-wide inclusive scan of c
    int lane = threadIdx.x & 31, w = threadIdx.x >> 5;
    int v = c;
    #pragma unroll
    for (int o = 1; o < 32; o <<= 1) {
        int u = __shfl_up_sync(0xffffffffu, v, o);
        if (lane >= o) v += u;
    }
    if (lane == 31) ws[w] = v;
    __syncthreads();
    if (w == 0) {
        int u = ws[lane];
        #pragma unroll
        for (int o = 1; o < 32; o <<= 1) {
            int x = __shfl_up_sync(0xffffffffu, u, o);
            if (lane >= o) u += x;
        }
        ws[lane] = u;
    }
    __syncthreads();
    int incl = v + ((w > 0) ? ws[w - 1] : 0);
    int total = ws[31];

    // publish aggregate / prefix
    if (threadIdx.x == 0) {
        if (tile == 0) {
            g_tpre[0] = total;
            __threadfence();
            g_tstate[0] = 2;
            s_exc = 0;
        } else {
            g_tagg[tile] = total;
            __threadfence();
            g_tstate[tile] = 1;
            // lookback
            int exc = 0;
            for (int tt = tile - 1; tt >= 0; tt--) {
                int st;
                while ((st = g_tstate[tt]) == 0) { }
                if (st == 2) { exc += g_tpre[tt]; break; }
                exc += g_tagg[tt];
            }
            g_tpre[tile] = exc + total;
            __threadfence();
            g_tstate[tile] = 2;
            s_exc = exc;
        }
    }
    __syncthreads();
    int r = s_exc + incl - c;   // global exclusive prefix
    if (i < E) { g_rowptr[i] = r; g_head[i] = r; }
    if (i == E - 1) g_rowptr[E] = r + c;   // == Mp
}

// -------- scatter: 4 pairs per thread, vector loads ----
__global__ void scatter_kernel(const void* __restrict__ idx, int Mp) {
    int m0 = (blockIdx.x * blockDim.x + threadIdx.x) * 4;
    if (m0 >= Mp) return;
    int is64 = g_idx64;
    int s[4], d[4], n = 0;
    if (m0 + 3 < Mp) {
        n = 4;
        if (is64) {
            const longlong2* ps = (const longlong2*)((const long long*)idx + m0);
            const longlong2* pd = (const longlong2*)((const long long*)idx + Mp + m0);
            longlong2 sa = ps[0], sb = ps[1], da = pd[0], db = pd[1];
            s[0] = (int)sa.x; s[1] = (int)sa.y; s[2] = (int)sb.x; s[3] = (int)sb.y;
            d[0] = (int)da.x; d[1] = (int)da.y; d[2] = (int)db.x; d[3] = (int)db.y;
        } else {
            int4 sa = *(const int4*)((const int*)idx + m0);
            int4 da = *(const int4*)((const int*)idx + Mp + m0);
            s[0] = sa.x; s[1] = sa.y; s[2] = sa.z; s[3] = sa.w;
            d[0] = da.x; d[1] = da.y; d[2] = da.z; d[3] = da.w;
        }
    } else {
        for (int r = 0; r < 4 && m0 + r < Mp; r++) {
            s[n] = ld_idx(idx, m0 + r, is64);
            d[n] = ld_idx(idx, (long long)Mp + m0 + r, is64);
            n++;
        }
    }
    #pragma unroll
    for (int r = 0; r < 4; r++) {
        if (r < n) {
            int pos = atomicAdd(&g_head[d[r]], 1);
            g_ssort[pos] = s[r];
        }
    }
}

// -------- agg: gather-only, warp per destination edge, fp16 Vh ----
__global__ void __launch_bounds__(256) agg_csr_kernel(float* __restrict__ out, int E) {
    int d = (blockIdx.x * 256 + threadIdx.x) >> 5;
    if (d >= E) return;
    int lane = threadIdx.x & 31;
    int h = lane >> 2;
    int beg = g_rowptr[d], end = g_rowptr[d + 1];

    float ax = 0.f, ay = 0.f, az = 0.f, aw = 0.f, sumw = 0.f;
    int s = (beg < end) ? g_ssort[beg] : 0;
    for (int p = beg; p < end; p++) {
        int s_next = (p + 1 < end) ? g_ssort[p + 1] : 0;
        float w = g_expk[s * 8 + h];
        uint2 u = *(const uint2*)(g_Vh + (size_t)s * 128 + lane * 4);
        float2 f01 = __half22float2(*reinterpret_cast<__half2*>(&u.x));
        float2 f23 = __half22float2(*reinterpret_cast<__half2*>(&u.y));
        ax += w * f01.x; ay += w * f01.y; az += w * f23.x; aw += w * f23.y;
        sumw += w;
        s = s_next;
    }
    float inv = __fdividef(1.f, sumw + 1e-16f);
    float4 o = make_float4(ax * inv, ay * inv, az * inv, aw * inv);
    *(float4*)(out + (size_t)d * 128 + lane * 4) = o;
}

extern "C" void kernel_launch(void* const* d_in, const int* in_sizes, int n_in,
                              void* d_out, int out_size) {
    const float* edge_attr = (const float*)d_in[0];
    const void*  idx       = d_in[1];
    // d_in[2]=Wq, d_in[3]=bq dead (softmax shift cancels Q)
    const float* Wk = (const float*)d_in[4];
    const float* bk = (const float*)d_in[5];
    const float* Wv = (const float*)d_in[6];
    const float* bv = (const float*)d_in[7];
    const float* Aw = (const float*)d_in[8];
    float* out = (float*)d_out;

    int E = in_sizes[0] / 128;
    int M = in_sizes[1] / 2;
    if (E > E_CAP) E = E_CAP;
    if (M > M_CAP) M = M_CAP;
    int NB = (E + 1023) / 1024;

    static cudaStream_t s1 = nullptr;
    static cudaEvent_t evFork = nullptr, evJoin = nullptr;
    static bool smem_set = false;
    if (!s1) {
        cudaStreamCreateWithFlags(&s1, cudaStreamNonBlocking);
        cudaEventCreateWithFlags(&evFork, cudaEventDisableTiming);
        cudaEventCreateWithFlags(&evJoin, cudaEventDisableTiming);
    }
    if (!smem_set) {
        cudaFuncSetAttribute(gemm_vh_tf32_kernel,
                             cudaFuncAttributeMaxDynamicSharedMemorySize,
                             SMEM_FLOATS * sizeof(float));
        smem_set = true;
    }

    // fork immediately
    cudaEventRecord(evFork, 0);
    cudaStreamWaitEvent(s1, evFork, 0);

    // chain A (stream 0): fused GEMM+kA (prep folded in)
    gemm_vh_tf32_kernel<<<(E + 127) / 128, 256, SMEM_FLOATS * sizeof(float), 0>>>(
        edge_attr, Wv, bv, Wk, bk, Aw, E);

    // chain B (stream s1): CSR build
    init_detect_kernel<<<(E + 255) / 256, 256, 0, s1>>>(idx, E);
    hist_kernel<<<(M / 4 + 255) / 256, 256, 0, s1>>>(idx, M);
    scan_lookback_kernel<<<NB, 1024, 0, s1>>>(E, M);
    scatter_kernel<<<(M / 4 + 255) / 256, 256, 0, s1>>>(idx, M);
    cudaEventRecord(evJoin, s1);

    // join, then aggregate on stream 0
    cudaStreamWaitEvent(0, evJoin, 0);
    agg_csr_kernel<<<(int)(((long long)E * 32 + 255) / 256), 256>>>(out, E);
}

// round 11
// speedup vs baseline: 1.0568x; 1.0568x over previous
#include <cuda_runtime.h>
#include <cuda_fp16.h>
#include <cstdint>

#define E_CAP 100000
#define M_CAP 1000000

// -------- device scratch --------
__device__ __half   g_Vh[(size_t)E_CAP * 128];   // V projection [E,128] fp16
__device__ float    g_expk[E_CAP * 8];           // exp(kA) per edge/head
__device__ int      g_cnt[E_CAP];                // per-dst counts (self-cleaning: scan1 re-zeroes)
__device__ int      g_rowptr[E_CAP + 1];         // CSR row pointers
__device__ int      g_head[E_CAP];               // scatter cursors
__device__ int      g_ssort[M_CAP];              // src ids sorted by dst
__device__ int      g_part[128];                 // scan partials

__device__ __forceinline__ int ld_idx(const void* idx, long long pos, int is64) {
    return is64 ? (int)((const long long*)idx)[pos] : ((const int*)idx)[pos];
}
// warp-parallel index-dtype detection: first 64 values read as int64 are all in
// [0,E) iff the data really is int64 (int32 data reinterpreted blows the range).
__device__ __forceinline__ int detect64(const void* idx, int E, int lane) {
    const long long* p = (const long long*)idx;
    long long v0 = p[lane], v1 = p[lane + 32];
    int ok = (v0 >= 0) && (v0 < (long long)E) && (v1 >= 0) && (v1 < (long long)E);
    return __all_sync(0xffffffffu, ok);
}
__device__ __forceinline__ unsigned f2tf(float f) {
    unsigned u; asm("cvt.rna.tf32.f32 %0, %1;" : "=r"(u) : "f"(f)); return u;
}
__device__ __forceinline__ void cp16(void* smem_dst, const void* gptr) {
    unsigned saddr = (unsigned)__cvta_generic_to_shared(smem_dst);
    asm volatile("cp.async.cg.shared.global [%0], [%1], 16;" :: "r"(saddr), "l"(gptr));
}

// -------- K1: Vh(fp16) = edge_attr @ Wv + bv  AND  expk = exp(edge_attr·wkA + bkA) ----
// tf32 mma.sync m16n8k8, cp.async double-buffered; Wk·Aw contraction folded into prologue.
#define AS_OFF 0
#define BS_OFF (2 * 128 * 36)
#define WK_OFF (BS_OFF + 2 * 32 * 132)
#define BK_OFF (WK_OFF + 8 * 132)
#define SMEM_FLOATS (BK_OFF + 8)

__global__ void __launch_bounds__(256) gemm_vh_tf32_kernel(
    const float* __restrict__ A, const float* __restrict__ B,
    const float* __restrict__ bias,
    const float* __restrict__ Wk, const float* __restrict__ bk,
    const float* __restrict__ Aw, int E)
{
    extern __shared__ float sm[];
    float* As  = sm + AS_OFF;   // buf*4608 + row*36 + k
    float* Bs  = sm + BS_OFF;   // buf*4224 + k*132 + n
    float* Wks = sm + WK_OFF;   // h*132 + k
    float* bks = sm + BK_OFF;

    const int t = threadIdx.x;
    const int warp = t >> 5, lane = t & 31;
    const int gid = lane >> 2, tid4 = lane & 3;
    const int wm = warp & 3, wn = warp >> 2;
    const int row0 = blockIdx.x * 128;

    const int a_row = t >> 3, a_c4 = t & 7;
    const int b_k   = t >> 5, b_n4 = t & 31;

    // prologue: prefetch chunk 0 into buf 0 (issue ASAP)
    {
        #pragma unroll
        for (int p = 0; p < 4; p++) {
            int row = a_row + p * 32;
            int grow = row0 + row; if (grow >= E) grow = E - 1;
            cp16(&As[row * 36 + a_c4 * 4], A + (size_t)grow * 128 + a_c4 * 4);
        }
        #pragma unroll
        for (int p = 0; p < 4; p++) {
            int kk = b_k + p * 8;
            cp16(&Bs[kk * 132 + b_n4 * 4], B + (size_t)kk * 128 + b_n4 * 4);
        }
        asm volatile("cp.async.commit_group;");
    }

    // folded prep: Wks[h][k] = sum_d Wk[k*128+h*16+d]*Aw[d*8+h]
    #pragma unroll
    for (int q = 0; q < 4; q++) {
        int i = t + q * 256;             // i = h*128 + k
        int h = i >> 7, k = i & 127;
        float s = 0.f;
        #pragma unroll
        for (int d = 0; d < 16; d++) s += Wk[k * 128 + h * 16 + d] * Aw[d * 8 + h];
        Wks[h * 132 + k] = s;
    }
    if (t < 8) {
        float s = 0.f;
        #pragma unroll
        for (int d = 0; d < 16; d++) s += bk[t * 16 + d] * Aw[d * 8 + t];
        bks[t] = s;
    }

    float c[2][8][4];
    #pragma unroll
    for (int i = 0; i < 2; i++)
        #pragma unroll
        for (int j = 0; j < 8; j++)
            #pragma unroll
            for (int r = 0; r < 4; r++) c[i][j][r] = 0.f;
    float kc[2][4] = {};

    #pragma unroll
    for (int i = 0; i < 4; i++) {
        const int k0 = i * 32;
        if (i < 3) {
            const int kn = k0 + 32;
            float* Ad = As + ((i + 1) & 1) * 4608;
            float* Bd = Bs + ((i + 1) & 1) * 4224;
            #pragma unroll
            for (int p = 0; p < 4; p++) {
                int row = a_row + p * 32;
                int grow = row0 + row; if (grow >= E) grow = E - 1;
                cp16(&Ad[row * 36 + a_c4 * 4], A + (size_t)grow * 128 + kn + a_c4 * 4);
            }
            #pragma unroll
            for (int p = 0; p < 4; p++) {
                int kk = b_k + p * 8;
                cp16(&Bd[kk * 132 + b_n4 * 4], B + (size_t)(kn + kk) * 128 + b_n4 * 4);
            }
            asm volatile("cp.async.commit_group;");
            asm volatile("cp.async.wait_group 1;");
        } else {
            asm volatile("cp.async.wait_group 0;");
        }
        __syncthreads();

        const float* Ab = As + (i & 1) * 4608;
        const float* Bb = Bs + (i & 1) * 4224;

        #pragma unroll
        for (int ks = 0; ks < 4; ks++) {
            const int kb = ks * 8;
            unsigned af[2][4];
            #pragma unroll
            for (int ma = 0; ma < 2; ma++) {
                int ar = wm * 32 + ma * 16;
                af[ma][0] = f2tf(Ab[(ar + gid    ) * 36 + kb + tid4]);
                af[ma][1] = f2tf(Ab[(ar + gid + 8) * 36 + kb + tid4]);
                af[ma][2] = f2tf(Ab[(ar + gid    ) * 36 + kb + tid4 + 4]);
                af[ma][3] = f2tf(Ab[(ar + gid + 8) * 36 + kb + tid4 + 4]);
            }
            #pragma unroll
            for (int na = 0; na < 8; na++) {
                int bc = wn * 64 + na * 8 + gid;
                unsigned b0 = f2tf(Bb[(kb + tid4    ) * 132 + bc]);
                unsigned b1 = f2tf(Bb[(kb + tid4 + 4) * 132 + bc]);
                #pragma unroll
                for (int ma = 0; ma < 2; ma++) {
                    asm volatile(
                        "mma.sync.aligned.m16n8k8.row.col.f32.tf32.tf32.f32 "
                        "{%0,%1,%2,%3}, {%4,%5,%6,%7}, {%8,%9}, {%0,%1,%2,%3};"
                        : "+f"(c[ma][na][0]), "+f"(c[ma][na][1]),
                          "+f"(c[ma][na][2]), "+f"(c[ma][na][3])
                        : "r"(af[ma][0]), "r"(af[ma][1]), "r"(af[ma][2]), "r"(af[ma][3]),
                          "r"(b0), "r"(b1));
                }
            }
            if (wn == 0) {   // fused kA: B2[k][h] = Wks[h][k]
                unsigned b0 = f2tf(Wks[gid * 132 + k0 + kb + tid4]);
                unsigned b1 = f2tf(Wks[gid * 132 + k0 + kb + tid4 + 4]);
                #pragma unroll
                for (int ma = 0; ma < 2; ma++) {
                    asm volatile(
                        "mma.sync.aligned.m16n8k8.row.col.f32.tf32.tf32.f32 "
                        "{%0,%1,%2,%3}, {%4,%5,%6,%7}, {%8,%9}, {%0,%1,%2,%3};"
                        : "+f"(kc[ma][0]), "+f"(kc[ma][1]),
                          "+f"(kc[ma][2]), "+f"(kc[ma][3])
                        : "r"(af[ma][0]), "r"(af[ma][1]), "r"(af[ma][2]), "r"(af[ma][3]),
                          "r"(b0), "r"(b1));
                }
            }
        }
        __syncthreads();
    }

    // epilogue: Vh = half(c + bias)
    #pragma unroll
    for (int ma = 0; ma < 2; ma++) {
        int r_base = row0 + wm * 32 + ma * 16 + gid;
        #pragma unroll
        for (int na = 0; na < 8; na++) {
            int col = wn * 64 + na * 8 + 2 * tid4;
            float b0 = bias[col], b1 = bias[col + 1];
            if (r_base < E) {
                __half2 p = __floats2half2_rn(c[ma][na][0] + b0, c[ma][na][1] + b1);
                *(__half2*)(g_Vh + (size_t)r_base * 128 + col) = p;
            }
            if (r_base + 8 < E) {
                __half2 p = __floats2half2_rn(c[ma][na][2] + b0, c[ma][na][3] + b1);
                *(__half2*)(g_Vh + (size_t)(r_base + 8) * 128 + col) = p;
            }
        }
    }
    if (wn == 0) {
        int h0 = 2 * tid4;
        float bk0 = bks[h0], bk1 = bks[h0 + 1];
        #pragma unroll
        for (int ma = 0; ma < 2; ma++) {
            int r = row0 + wm * 32 + ma * 16 + gid;
            if (r < E) {
                g_expk[r * 8 + h0    ] = __expf(kc[ma][0] + bk0);
                g_expk[r * 8 + h0 + 1] = __expf(kc[ma][1] + bk1);
            }
            if (r + 8 < E) {
                g_expk[(r + 8) * 8 + h0    ] = __expf(kc[ma][2] + bk0);
                g_expk[(r + 8) * 8 + h0 + 1] = __expf(kc[ma][3] + bk1);
            }
        }
    }
}

// -------- hist: 1 pair/thread, per-warp inline dtype detect (g_cnt pre-zeroed) ----
__global__ void hist_kernel(const void* __restrict__ idx, int E, int Mp) {
    int lane = threadIdx.x & 31;
    int is64 = detect64(idx, E, lane);
    int m = blockIdx.x * blockDim.x + threadIdx.x;
    if (m >= Mp) return;
    int d = ld_idx(idx, (long long)Mp + m, is64);
    atomicAdd(&g_cnt[d], 1);
}

// -------- scan1: block-local scan; self-cleans g_cnt for the next launch ----
__global__ void __launch_bounds__(1024) scan1_kernel(int E) {
    int i = blockIdx.x * 1024 + threadIdx.x;
    int c = (i < E) ? g_cnt[i] : 0;
    if (i < E) g_cnt[i] = 0;                 // restore invariant for next replay
    int lane = threadIdx.x & 31, w = threadIdx.x >> 5;
    int v = c;
    #pragma unroll
    for (int o = 1; o < 32; o <<= 1) {
        int t = __shfl_up_sync(0xffffffffu, v, o);
        if (lane >= o) v += t;
    }
    __shared__ int ws[32];
    if (lane == 31) ws[w] = v;
    __syncthreads();
    if (w == 0) {
        int t = ws[lane];
        #pragma unroll
        for (int o = 1; o < 32; o <<= 1) {
            int u = __shfl_up_sync(0xffffffffu, t, o);
            if (lane >= o) t += u;
        }
        ws[lane] = t;
    }
    __syncthreads();
    int off = (w > 0) ? ws[w - 1] : 0;
    int incl = v + off;
    if (i < E) g_rowptr[i] = incl - c;       // block-local exclusive
    if (threadIdx.x == 1023) g_part[blockIdx.x] = incl;
}

// -------- scan23: every block scans the partials redundantly, then applies ----
__global__ void __launch_bounds__(256) scan23_kernel(int NB, int Mp, int E) {
    __shared__ int sh[128];
    int t = threadIdx.x;
    if (t < 128) sh[t] = (t < NB) ? g_part[t] : 0;
    __syncthreads();
    #pragma unroll
    for (int o = 1; o < 128; o <<= 1) {
        int u = (t < 128 && t >= o) ? sh[t - o] : 0;
        __syncthreads();
        if (t < 128) sh[t] += u;
        __syncthreads();
    }
    int i = blockIdx.x * 256 + t;
    if (i < E) {
        int b = i >> 10;
        int r = g_rowptr[i] + ((b > 0) ? sh[b - 1] : 0);
        g_rowptr[i] = r;
        g_head[i] = r;
    }
    if (i == 0) g_rowptr[E] = Mp;
}

// -------- scatter: 1 pair/thread, per-warp inline dtype detect ----
__global__ void scatter_kernel(const void* __restrict__ idx, int E, int Mp) {
    int lane = threadIdx.x & 31;
    int is64 = detect64(idx, E, lane);
    int m = blockIdx.x * blockDim.x + threadIdx.x;
    if (m >= Mp) return;
    int s = ld_idx(idx, m, is64);
    int d = ld_idx(idx, (long long)Mp + m, is64);
    int pos = atomicAdd(&g_head[d], 1);
    g_ssort[pos] = s;
}

// -------- agg: gather-only, warp per destination edge, fp16 Vh ----
__global__ void __launch_bounds__(256) agg_csr_kernel(float* __restrict__ out, int E) {
    int d = (blockIdx.x * 256 + threadIdx.x) >> 5;
    if (d >= E) return;
    int lane = threadIdx.x & 31;
    int h = lane >> 2;
    int beg = g_rowptr[d], end = g_rowptr[d + 1];

    float ax = 0.f, ay = 0.f, az = 0.f, aw = 0.f, sumw = 0.f;
    int s = (beg < end) ? g_ssort[beg] : 0;
    for (int p = beg; p < end; p++) {
        int s_next = (p + 1 < end) ? g_ssort[p + 1] : 0;
        float w = g_expk[s * 8 + h];
        uint2 u = *(const uint2*)(g_Vh + (size_t)s * 128 + lane * 4);
        float2 f01 = __half22float2(*reinterpret_cast<__half2*>(&u.x));
        float2 f23 = __half22float2(*reinterpret_cast<__half2*>(&u.y));
        ax += w * f01.x; ay += w * f01.y; az += w * f23.x; aw += w * f23.y;
        sumw += w;
        s = s_next;
    }
    float inv = __fdividef(1.f, sumw + 1e-16f);
    float4 o = make_float4(ax * inv, ay * inv, az * inv, aw * inv);
    *(float4*)(out + (size_t)d * 128 + lane * 4) = o;
}

extern "C" void kernel_launch(void* const* d_in, const int* in_sizes, int n_in,
                              void* d_out, int out_size) {
    const float* edge_attr = (const float*)d_in[0];
    const void*  idx       = d_in[1];
    // d_in[2]=Wq, d_in[3]=bq dead (softmax shift cancels Q)
    const float* Wk = (const float*)d_in[4];
    const float* bk = (const float*)d_in[5];
    const float* Wv = (const float*)d_in[6];
    const float* bv = (const float*)d_in[7];
    const float* Aw = (const float*)d_in[8];
    float* out = (float*)d_out;

    int E = in_sizes[0] / 128;
    int M = in_sizes[1] / 2;
    if (E > E_CAP) E = E_CAP;
    if (M > M_CAP) M = M_CAP;
    int NB = (E + 1023) / 1024;

    static cudaStream_t s1 = nullptr;
    static cudaEvent_t evFork = nullptr, evJoin = nullptr;
    static bool smem_set = false;
    if (!s1) {
        cudaStreamCreateWithFlags(&s1, cudaStreamNonBlocking);
        cudaEventCreateWithFlags(&evFork, cudaEventDisableTiming);
        cudaEventCreateWithFlags(&evJoin, cudaEventDisableTiming);
    }
    if (!smem_set) {
        cudaFuncSetAttribute(gemm_vh_tf32_kernel,
                             cudaFuncAttributeMaxDynamicSharedMemorySize,
                             SMEM_FLOATS * sizeof(float));
        smem_set = true;
    }

    // fork immediately
    cudaEventRecord(evFork, 0);
    cudaStreamWaitEvent(s1, evFork, 0);

    // chain A (stream 0): fused GEMM + kA (prep folded in)
    gemm_vh_tf32_kernel<<<(E + 127) / 128, 256, SMEM_FLOATS * sizeof(float), 0>>>(
        edge_attr, Wv, bv, Wk, bk, Aw, E);

    // chain B (stream s1): CSR build (g_cnt arrives zeroed; scan1 re-zeroes it)
    hist_kernel<<<(M + 255) / 256, 256, 0, s1>>>(idx, E, M);
    scan1_kernel<<<NB, 1024, 0, s1>>>(E);
    scan23_kernel<<<(E + 255) / 256, 256, 0, s1>>>(NB, M, E);
    scatter_kernel<<<(M + 255) / 256, 256, 0, s1>>>(idx, E, M);
    cudaEventRecord(evJoin, s1);

    // join, then aggregate on stream 0
    cudaStreamWaitEvent(0, evJoin, 0);
    agg_csr_kernel<<<(int)(((long long)E * 32 + 255) / 256), 256>>>(out, E);
}

// round 12
// speedup vs baseline: 1.4184x; 1.3421x over previous
#include <cuda_runtime.h>
#include <cuda_fp16.h>
#include <cstdint>

#define E_CAP 100000
#define M_CAP 1000000

// -------- device scratch --------
__device__ __half   g_Vh[(size_t)E_CAP * 128];   // V projection [E,128] fp16
__device__ float    g_expk[E_CAP * 8];           // exp(kA) per edge/head
__device__ float    g_wkAT[8 * 128];             // pre-contracted Wk·Aw, [h][k]
__device__ float    g_bkA[8];
__device__ int      g_cnt[E_CAP];                // per-dst pair counts
__device__ int      g_rowptr[E_CAP + 1];         // CSR row pointers
__device__ int      g_head[E_CAP];               // scatter cursors
__device__ int      g_ssort[M_CAP];              // src ids sorted by dst
__device__ int      g_part[128];                 // scan partials
__device__ int      g_idx64;

__device__ __forceinline__ int ld_idx(const void* idx, long long pos, int is64) {
    return is64 ? (int)((const long long*)idx)[pos] : ((const int*)idx)[pos];
}
__device__ __forceinline__ unsigned f2tf(float f) {
    unsigned u; asm("cvt.rna.tf32.f32 %0, %1;" : "=r"(u) : "f"(f)); return u;
}
__device__ __forceinline__ void cp16(void* smem_dst, const void* gptr) {
    unsigned saddr = (unsigned)__cvta_generic_to_shared(smem_dst);
    asm volatile("cp.async.cg.shared.global [%0], [%1], 16;" :: "r"(saddr), "l"(gptr));
}

// -------- K0: pre-contract Wk with Aw (Q is algebraically dead; softmax shift cancels) --
__global__ void prep_kernel(const float* __restrict__ Wk, const float* __restrict__ bk,
                            const float* __restrict__ Aw) {
    int k = threadIdx.x;
    if (k < 128) {
        #pragma unroll
        for (int h = 0; h < 8; h++) {
            float s = 0.f;
            #pragma unroll
            for (int d = 0; d < 16; d++) s += Wk[k * 128 + h * 16 + d] * Aw[d * 8 + h];
            g_wkAT[h * 128 + k] = s;
        }
    }
    if (k < 8) {
        float s = 0.f;
        #pragma unroll
        for (int d = 0; d < 16; d++) s += bk[k * 16 + d] * Aw[d * 8 + k];
        g_bkA[k] = s;
    }
}

// -------- merged: zero per-dst counters + detect index dtype ----
__global__ void init_detect_kernel(const void* __restrict__ idx, int E) {
    int i = blockIdx.x * blockDim.x + threadIdx.x;
    if (i < E) g_cnt[i] = 0;
    if (i == 0) {
        const long long* p = (const long long*)idx;
        int ok = 1;
        for (int q = 0; q < 64; q++) {
            long long v = p[q];
            if (v < 0 || v >= (long long)E) { ok = 0; break; }
        }
        g_idx64 = ok;
    }
}

// -------- K1: Vh(fp16) = edge_attr @ Wv + bv  AND  expk = exp(edge_attr·wkA + bkA) ----
// tf32 mma.sync m16n8k8, cp.async double-buffered, kA fused as 8 extra N columns.
#define AS_OFF 0
#define BS_OFF (2 * 128 * 36)
#define WK_OFF (BS_OFF + 2 * 32 * 132)
#define BK_OFF (WK_OFF + 8 * 132)
#define SMEM_FLOATS (BK_OFF + 8)

__global__ void __launch_bounds__(256) gemm_vh_tf32_kernel(
    const float* __restrict__ A, const float* __restrict__ B,
    const float* __restrict__ bias, int E)
{
    extern __shared__ float sm[];
    float* As  = sm + AS_OFF;   // buf*4608 + row*36 + k
    float* Bs  = sm + BS_OFF;   // buf*4224 + k*132 + n
    float* Wks = sm + WK_OFF;   // h*132 + k
    float* bks = sm + BK_OFF;

    const int t = threadIdx.x;
    const int warp = t >> 5, lane = t & 31;
    const int gid = lane >> 2, tid4 = lane & 3;
    const int wm = warp & 3, wn = warp >> 2;
    const int row0 = blockIdx.x * 128;

    for (int i = t; i < 1024; i += 256) Wks[(i >> 7) * 132 + (i & 127)] = g_wkAT[i];
    if (t < 8) bks[t] = g_bkA[t];

    float c[2][8][4];
    #pragma unroll
    for (int i = 0; i < 2; i++)
        #pragma unroll
        for (int j = 0; j < 8; j++)
            #pragma unroll
            for (int r = 0; r < 4; r++) c[i][j][r] = 0.f;
    float kc[2][4] = {};

    const int a_row = t >> 3, a_c4 = t & 7;
    const int b_k   = t >> 5, b_n4 = t & 31;

    {
        #pragma unroll
        for (int p = 0; p < 4; p++) {
            int row = a_row + p * 32;
            int grow = row0 + row; if (grow >= E) grow = E - 1;
            cp16(&As[row * 36 + a_c4 * 4], A + (size_t)grow * 128 + a_c4 * 4);
        }
        #pragma unroll
        for (int p = 0; p < 4; p++) {
            int kk = b_k + p * 8;
            cp16(&Bs[kk * 132 + b_n4 * 4], B + (size_t)kk * 128 + b_n4 * 4);
        }
        asm volatile("cp.async.commit_group;");
    }

    #pragma unroll
    for (int i = 0; i < 4; i++) {
        const int k0 = i * 32;
        if (i < 3) {
            const int kn = k0 + 32;
            float* Ad = As + ((i + 1) & 1) * 4608;
            float* Bd = Bs + ((i + 1) & 1) * 4224;
            #pragma unroll
            for (int p = 0; p < 4; p++) {
                int row = a_row + p * 32;
                int grow = row0 + row; if (grow >= E) grow = E - 1;
                cp16(&Ad[row * 36 + a_c4 * 4], A + (size_t)grow * 128 + kn + a_c4 * 4);
            }
            #pragma unroll
            for (int p = 0; p < 4; p++) {
                int kk = b_k + p * 8;
                cp16(&Bd[kk * 132 + b_n4 * 4], B + (size_t)(kn + kk) * 128 + b_n4 * 4);
            }
            asm volatile("cp.async.commit_group;");
            asm volatile("cp.async.wait_group 1;");
        } else {
            asm volatile("cp.async.wait_group 0;");
        }
        __syncthreads();

        const float* Ab = As + (i & 1) * 4608;
        const float* Bb = Bs + (i & 1) * 4224;

        #pragma unroll
        for (int ks = 0; ks < 4; ks++) {
            const int kb = ks * 8;
            unsigned af[2][4];
            #pragma unroll
            for (int ma = 0; ma < 2; ma++) {
                int ar = wm * 32 + ma * 16;
                af[ma][0] = f2tf(Ab[(ar + gid    ) * 36 + kb + tid4]);
                af[ma][1] = f2tf(Ab[(ar + gid + 8) * 36 + kb + tid4]);
                af[ma][2] = f2tf(Ab[(ar + gid    ) * 36 + kb + tid4 + 4]);
                af[ma][3] = f2tf(Ab[(ar + gid + 8) * 36 + kb + tid4 + 4]);
            }
            #pragma unroll
            for (int na = 0; na < 8; na++) {
                int bc = wn * 64 + na * 8 + gid;
                unsigned b0 = f2tf(Bb[(kb + tid4    ) * 132 + bc]);
                unsigned b1 = f2tf(Bb[(kb + tid4 + 4) * 132 + bc]);
                #pragma unroll
                for (int ma = 0; ma < 2; ma++) {
                    asm volatile(
                        "mma.sync.aligned.m16n8k8.row.col.f32.tf32.tf32.f32 "
                        "{%0,%1,%2,%3}, {%4,%5,%6,%7}, {%8,%9}, {%0,%1,%2,%3};"
                        : "+f"(c[ma][na][0]), "+f"(c[ma][na][1]),
                          "+f"(c[ma][na][2]), "+f"(c[ma][na][3])
                        : "r"(af[ma][0]), "r"(af[ma][1]), "r"(af[ma][2]), "r"(af[ma][3]),
                          "r"(b0), "r"(b1));
                }
            }
            if (wn == 0) {   // fused kA: B2[k][h] = Wks[h][k]
                unsigned b0 = f2tf(Wks[gid * 132 + k0 + kb + tid4]);
                unsigned b1 = f2tf(Wks[gid * 132 + k0 + kb + tid4 + 4]);
                #pragma unroll
                for (int ma = 0; ma < 2; ma++) {
                    asm volatile(
                        "mma.sync.aligned.m16n8k8.row.col.f32.tf32.tf32.f32 "
                        "{%0,%1,%2,%3}, {%4,%5,%6,%7}, {%8,%9}, {%0,%1,%2,%3};"
                        : "+f"(kc[ma][0]), "+f"(kc[ma][1]),
                          "+f"(kc[ma][2]), "+f"(kc[ma][3])
                        : "r"(af[ma][0]), "r"(af[ma][1]), "r"(af[ma][2]), "r"(af[ma][3]),
                          "r"(b0), "r"(b1));
                }
            }
        }
        __syncthreads();
    }

    // epilogue: Vh = half(c + bias)
    #pragma unroll
    for (int ma = 0; ma < 2; ma++) {
        int r_base = row0 + wm * 32 + ma * 16 + gid;
        #pragma unroll
        for (int na = 0; na < 8; na++) {
            int col = wn * 64 + na * 8 + 2 * tid4;
            float b0 = bias[col], b1 = bias[col + 1];
            if (r_base < E) {
                __half2 p = __floats2half2_rn(c[ma][na][0] + b0, c[ma][na][1] + b1);
                *(__half2*)(g_Vh + (size_t)r_base * 128 + col) = p;
            }
            if (r_base + 8 < E) {
                __half2 p = __floats2half2_rn(c[ma][na][2] + b0, c[ma][na][3] + b1);
                *(__half2*)(g_Vh + (size_t)(r_base + 8) * 128 + col) = p;
            }
        }
    }
    if (wn == 0) {
        int h0 = 2 * tid4;
        float bk0 = bks[h0], bk1 = bks[h0 + 1];
        #pragma unroll
        for (int ma = 0; ma < 2; ma++) {
            int r = row0 + wm * 32 + ma * 16 + gid;
            if (r < E) {
                g_expk[r * 8 + h0    ] = __expf(kc[ma][0] + bk0);
                g_expk[r * 8 + h0 + 1] = __expf(kc[ma][1] + bk1);
            }
            if (r + 8 < E) {
                g_expk[(r + 8) * 8 + h0    ] = __expf(kc[ma][2] + bk0);
                g_expk[(r + 8) * 8 + h0 + 1] = __expf(kc[ma][3] + bk1);
            }
        }
    }
}

// -------- CSR build --------
__global__ void hist_kernel(const void* __restrict__ idx, int Mp) {
    int m = blockIdx.x * blockDim.x + threadIdx.x;
    if (m >= Mp) return;
    int d = ld_idx(idx, (long long)Mp + m, g_idx64);
    atomicAdd(&g_cnt[d], 1);
}

__global__ void __launch_bounds__(1024) scan1_kernel(int E) {
    int i = blockIdx.x * 1024 + threadIdx.x;
    int c = (i < E) ? g_cnt[i] : 0;
    int lane = threadIdx.x & 31, w = threadIdx.x >> 5;
    int v = c;
    #pragma unroll
    for (int o = 1; o < 32; o <<= 1) {
        int t = __shfl_up_sync(0xffffffffu, v, o);
        if (lane >= o) v += t;
    }
    __shared__ int ws[32];
    if (lane == 31) ws[w] = v;
    __syncthreads();
    if (w == 0) {
        int t = ws[lane];
        #pragma unroll
        for (int o = 1; o < 32; o <<= 1) {
            int u = __shfl_up_sync(0xffffffffu, t, o);
            if (lane >= o) t += u;
        }
        ws[lane] = t;
    }
    __syncthreads();
    int off = (w > 0) ? ws[w - 1] : 0;
    int incl = v + off;
    if (i < E) g_rowptr[i] = incl - c;
    if (threadIdx.x == 1023) g_part[blockIdx.x] = incl;
}

__global__ void scan2_kernel(int NB, int Mp, int E) {
    __shared__ int sh[128];
    int t = threadIdx.x;
    int v = (t < NB) ? g_part[t] : 0;
    sh[t] = v;
    __syncthreads();
    #pragma unroll
    for (int o = 1; o < 128; o <<= 1) {
        int u = (t >= o) ? sh[t - o] : 0;
        __syncthreads();
        sh[t] += u;
        __syncthreads();
    }
    if (t < NB) g_part[t] = sh[t] - v;
    if (t == 0) g_rowptr[E] = Mp;
}

__global__ void scan3_kernel(int E) {
    int i = blockIdx.x * blockDim.x + threadIdx.x;
    if (i >= E) return;
    int r = g_rowptr[i] + g_part[i >> 10];
    g_rowptr[i] = r;
    g_head[i] = r;
}

__global__ void scatter_kernel(const void* __restrict__ idx, int Mp) {
    int m = blockIdx.x * blockDim.x + threadIdx.x;
    if (m >= Mp) return;
    int is64 = g_idx64;
    int s = ld_idx(idx, m, is64);
    int d = ld_idx(idx, (long long)Mp + m, is64);
    int pos = atomicAdd(&g_head[d], 1);
    g_ssort[pos] = s;
}

// -------- agg: gather-only, warp per destination edge, fp16 Vh, 2-deep pipeline ----
__global__ void __launch_bounds__(256) agg_csr_kernel(float* __restrict__ out, int E) {
    int d = (blockIdx.x * 256 + threadIdx.x) >> 5;
    if (d >= E) return;
    int lane = threadIdx.x & 31;
    int h = lane >> 2;
    int beg = g_rowptr[d], end = g_rowptr[d + 1];

    float ax = 0.f, ay = 0.f, az = 0.f, aw = 0.f, sumw = 0.f;
    if (beg < end) {
        int s = g_ssort[beg];
        float w = g_expk[s * 8 + h];
        uint2 u = *(const uint2*)(g_Vh + (size_t)s * 128 + lane * 4);
        for (int p = beg + 1; p < end; p++) {
            // issue next iteration's gathers before consuming current values
            int s_n = g_ssort[p];
            float w_n = g_expk[s_n * 8 + h];
            uint2 u_n = *(const uint2*)(g_Vh + (size_t)s_n * 128 + lane * 4);
            float2 f01 = __half22float2(*reinterpret_cast<__half2*>(&u.x));
            float2 f23 = __half22float2(*reinterpret_cast<__half2*>(&u.y));
            ax += w * f01.x; ay += w * f01.y; az += w * f23.x; aw += w * f23.y;
            sumw += w;
            w = w_n; u = u_n;
        }
        float2 f01 = __half22float2(*reinterpret_cast<__half2*>(&u.x));
        float2 f23 = __half22float2(*reinterpret_cast<__half2*>(&u.y));
        ax += w * f01.x; ay += w * f01.y; az += w * f23.x; aw += w * f23.y;
        sumw += w;
    }
    float inv = __fdividef(1.f, sumw + 1e-16f);
    float4 o = make_float4(ax * inv, ay * inv, az * inv, aw * inv);
    *(float4*)(out + (size_t)d * 128 + lane * 4) = o;
}

extern "C" void kernel_launch(void* const* d_in, const int* in_sizes, int n_in,
                              void* d_out, int out_size) {
    const float* edge_attr = (const float*)d_in[0];
    const void*  idx       = d_in[1];
    // d_in[2]=Wq, d_in[3]=bq dead (softmax shift cancels Q)
    const float* Wk = (const float*)d_in[4];
    const float* bk = (const float*)d_in[5];
    const float* Wv = (const float*)d_in[6];
    const float* bv = (const float*)d_in[7];
    const float* Aw = (const float*)d_in[8];
    float* out = (float*)d_out;

    int E = in_sizes[0] / 128;
    int M = in_sizes[1] / 2;
    if (E > E_CAP) E = E_CAP;
    if (M > M_CAP) M = M_CAP;
    int NB = (E + 1023) / 1024;

    static cudaStream_t s1 = nullptr;
    static cudaEvent_t evFork = nullptr, evJoin = nullptr;
    static bool smem_set = false;
    if (!s1) {
        cudaStreamCreateWithFlags(&s1, cudaStreamNonBlocking);
        cudaEventCreateWithFlags(&evFork, cudaEventDisableTiming);
        cudaEventCreateWithFlags(&evJoin, cudaEventDisableTiming);
    }
    if (!smem_set) {
        cudaFuncSetAttribute(gemm_vh_tf32_kernel,
                             cudaFuncAttributeMaxDynamicSharedMemorySize,
                             SMEM_FLOATS * sizeof(float));
        smem_set = true;
    }

    // fork immediately: chain A never needs the index dtype
    cudaEventRecord(evFork, 0);
    cudaStreamWaitEvent(s1, evFork, 0);

    // chain A (stream 0): prep -> fused GEMM+kA
    prep_kernel<<<1, 128>>>(Wk, bk, Aw);
    gemm_vh_tf32_kernel<<<(E + 127) / 128, 256, SMEM_FLOATS * sizeof(float), 0>>>(
        edge_attr, Wv, bv, E);

    // chain B (stream s1): CSR build
    init_detect_kernel<<<(E + 255) / 256, 256, 0, s1>>>(idx, E);
    hist_kernel<<<(M + 255) / 256, 256, 0, s1>>>(idx, M);
    scan1_kernel<<<NB, 1024, 0, s1>>>(E);
    scan2_kernel<<<1, 128, 0, s1>>>(NB, M, E);
    scan3_kernel<<<(E + 255) / 256, 256, 0, s1>>>(E);
    scatter_kernel<<<(M + 255) / 256, 256, 0, s1>>>(idx, M);
    cudaEventRecord(evJoin, s1);

    // join, then aggregate on stream 0
    cudaStreamWaitEvent(0, evJoin, 0);
    agg_csr_kernel<<<(int)(((long long)E * 32 + 255) / 256), 256>>>(out, E);
}